// round 2
// baseline (speedup 1.0000x reference)
#include <cuda_runtime.h>
#include <cstdint>

#define DTc 0.0005f
#define BS 1024
#define Bc 25
#define NBc 26
#define Fc 15
#define SPFc 10
#define ND 32      // 7 + B
#define NDD 31     // 6 + B
#define RFROW 156  // (B+1)*6

#define ROOT_BLOCKS 128
#define ROOT_WPB 8
#define JBLK_PER_F 100            // 25600 / 256
#define J_BLOCKS (Fc * JBLK_PER_F)

// ---- device scratch (static; no allocation) ----
__device__ float2 g_Y[Fc * BS * Bc];           // per-frame chunk affine offsets
__device__ float2 g_jsnap[(Fc + 1) * BS * Bc]; // (jq, jqd) at frame boundaries
__device__ float  g_root[(Fc + 1) * BS * 16];  // root p,q,w,v (13 used) per frame

__device__ __forceinline__ void cp4(float* dst, const float* src) {
    unsigned d = (unsigned)__cvta_generic_to_shared(dst);
    asm volatile("cp.async.ca.shared.global [%0], [%1], 4;\n" :: "r"(d), "l"(src));
}
__device__ __forceinline__ void cp_commit() { asm volatile("cp.async.commit_group;\n"); }
__device__ __forceinline__ void cp_wait0()  { asm volatile("cp.async.wait_group 0;\n"); }

__device__ __forceinline__ void quat_mul(
    float ax, float ay, float az, float aw,
    float bx, float by, float bz, float bw,
    float& rx, float& ry, float& rz, float& rw)
{
    rx = aw*bx + ax*bw + ay*bz - az*by;
    ry = aw*by - ax*bz + ay*bw + az*bx;
    rz = aw*bz + ax*by - ay*bx + az*bw;
    rw = aw*bw - ax*bx - ay*by - az*bz;
}

__device__ __forceinline__ void quat_rot(
    float qx, float qy, float qz, float qw,
    float vx, float vy, float vz,
    float& rx, float& ry, float& rz)
{
    float tx = 2.f*(qy*vz - qz*vy);
    float ty = 2.f*(qz*vx - qx*vz);
    float tz = 2.f*(qx*vy - qy*vx);
    rx = vx + qw*tx + (qy*tz - qz*ty);
    ry = vy + qw*ty + (qz*tx - qx*tz);
    rz = vz + qw*tz + (qx*ty - qy*tx);
}

#define SCAN3(X, Y, Z, lane)                                              \
    _Pragma("unroll")                                                     \
    for (int _o = 1; _o < 32; _o <<= 1) {                                 \
        float _tx = __shfl_up_sync(0xffffffffu, X, _o);                   \
        float _ty = __shfl_up_sync(0xffffffffu, Y, _o);                   \
        float _tz = __shfl_up_sync(0xffffffffu, Z, _o);                   \
        if ((lane) >= _o) { X += _tx; Y += _ty; Z += _tz; }               \
    }

// ===================== K1: time-chunk joint integration + root chain =====================

__device__ __forceinline__ void stage_root(
    float* __restrict__ buf, int lane, int f, int b,
    const float* __restrict__ torques, const float* __restrict__ res_f)
{
    const int s0 = f * SPFc;
    #pragma unroll
    for (int s = 0; s < SPFc; s++) {
        const float* rT = torques + ((size_t)(s0 + s) * BS + b) * NDD;
        const float* rF = res_f   + ((size_t)(s0 + s) * BS + b) * RFROW;
        if (lane < 6)       cp4(buf + s*12 + lane, rT + lane);
        else if (lane < 12) cp4(buf + s*12 + lane, rF + (lane - 6));
    }
}

__global__ void __launch_bounds__(256)
k1_integrate(const float* __restrict__ q_init, const float* __restrict__ qd_init,
             const float* __restrict__ torques, const float* __restrict__ res_f,
             const float* __restrict__ refs, const float* __restrict__ tke,
             const float* __restrict__ tkd, const float* __restrict__ bmass,
             const float* __restrict__ jaxes)
{
    __shared__ float sroot[ROOT_WPB][2][SPFc * 12];

    if (blockIdx.x < ROOT_BLOCKS) {
        // ---------------- root integration: one warp per batch element ----------------
        const int warp = threadIdx.x >> 5;
        const int lane = threadIdx.x & 31;
        const int b = blockIdx.x * ROOT_WPB + warp;

        float px = q_init[b*ND + 0], py = q_init[b*ND + 1], pz = q_init[b*ND + 2];
        float qx = q_init[b*ND + 3], qy = q_init[b*ND + 4], qz = q_init[b*ND + 5], qw = q_init[b*ND + 6];
        {
            float n2 = qx*qx + qy*qy + qz*qz + qw*qw;
            float inv = rsqrtf(fmaxf(n2, 1e-16f));
            qx *= inv; qy *= inv; qz *= inv; qw *= inv;
        }
        float wx = qd_init[b*NDD + 0], wy = qd_init[b*NDD + 1], wz = qd_init[b*NDD + 2];
        float vx = qd_init[b*NDD + 3], vy = qd_init[b*NDD + 4], vz = qd_init[b*NDD + 5];
        const float invm0 = 1.f / (bmass[b*NBc + 0] + 0.1f);

        if (lane == 0) {
            float* d = g_root + (size_t)b * 16;
            d[0]=px; d[1]=py; d[2]=pz; d[3]=qx; d[4]=qy; d[5]=qz; d[6]=qw;
            d[7]=wx; d[8]=wy; d[9]=wz; d[10]=vx; d[11]=vy; d[12]=vz;
        }

        float* buf0 = sroot[warp][0];
        float* buf1 = sroot[warp][1];
        stage_root(buf0, lane, 0, b, torques, res_f);
        cp_commit(); cp_wait0(); __syncwarp();

        for (int f = 0; f < Fc; f++) {
            float* cur = (f & 1) ? buf1 : buf0;
            float* nxt = (f & 1) ? buf0 : buf1;
            if (f + 1 < Fc) { stage_root(nxt, lane, f + 1, b, torques, res_f); cp_commit(); }

            #pragma unroll
            for (int s = 0; s < SPFc; s++) {
                const float* u = cur + s * 12;
                vx += DTc * ((u[3] + u[9])  * invm0);
                vy += DTc * ((u[4] + u[10]) * invm0);
                vz += DTc * ((u[5] + u[11]) * invm0 - 9.81f);
                wx += DTc * ((u[0] + u[6]) * invm0);
                wy += DTc * ((u[1] + u[7]) * invm0);
                wz += DTc * ((u[2] + u[8]) * invm0);
                px += DTc * vx; py += DTc * vy; pz += DTc * vz;
                float mx =  wx*qw + wy*qz - wz*qy;
                float my = -wx*qz + wy*qw + wz*qx;
                float mz =  wx*qy - wy*qx + wz*qw;
                float mw = -(wx*qx + wy*qy + wz*qz);
                qx += 0.5f * DTc * mx; qy += 0.5f * DTc * my;
                qz += 0.5f * DTc * mz; qw += 0.5f * DTc * mw;
                float n2 = qx*qx + qy*qy + qz*qz + qw*qw;
                float inv = rsqrtf(fmaxf(n2, 1e-16f));
                qx *= inv; qy *= inv; qz *= inv; qw *= inv;
            }

            if (lane == 0) {
                float* d = g_root + ((size_t)(f + 1) * BS + b) * 16;
                d[0]=px; d[1]=py; d[2]=pz; d[3]=qx; d[4]=qy; d[5]=qz; d[6]=qw;
                d[7]=wx; d[8]=wy; d[9]=wz; d[10]=vx; d[11]=vy; d[12]=vz;
            }
            if (f + 1 < Fc) { cp_wait0(); __syncwarp(); }
        }
    } else {
        // ---------------- joint chunks: thread = (frame f, batch b, joint j) ----------------
        const int jb = blockIdx.x - ROOT_BLOCKS;
        const int f = jb / JBLK_PER_F;
        const int r = (jb % JBLK_PER_F) * 256 + threadIdx.x;  // 0..25599
        const int b = r / Bc;
        const int j = r - b * Bc;

        const float ke = tke[r];
        const float kd = tkd[r];
        const float invm = 1.f / (bmass[b*NBc + 1 + j] + 0.1f);
        const float al = DTc * invm * ke;       // alpha
        const float Bb = 1.f - DTc * invm * kd; // 1 - kappa
        float a0 = jaxes[j*3 + 0], a1 = jaxes[j*3 + 1], a2 = jaxes[j*3 + 2];
        {
            float n = fmaxf(sqrtf(a0*a0 + a1*a1 + a2*a2), 1e-8f);
            a0 /= n; a1 /= n; a2 /= n;
        }

        float Y1 = 0.f, Y2 = 0.f;
        const int s0 = f * SPFc;
        #pragma unroll
        for (int h = 0; h < 2; h++) {
            float tv[5], rv[5], f0[5], f1[5], f2[5];
            #pragma unroll
            for (int k = 0; k < 5; k++) {
                const int s = s0 + h*5 + k;
                const size_t rowT = ((size_t)s * BS + b) * NDD;
                tv[k] = torques[rowT + 6 + j];
                rv[k] = refs[rowT + 6 + j];
                const size_t rowF = (((size_t)s * BS + b) * NBc + 1 + j) * 6;
                f0[k] = res_f[rowF + 0];
                f1[k] = res_f[rowF + 1];
                f2[k] = res_f[rowF + 2];
            }
            #pragma unroll
            for (int k = 0; k < 5; k++) {
                float c = DTc * invm * (tv[k] + ke * rv[k] + f0[k]*a0 + f1[k]*a1 + f2[k]*a2);
                float y2 = fmaf(-al, Y1, fmaf(Bb, Y2, c));
                Y1 = fmaf(DTc, y2, Y1);
                Y2 = y2;
            }
        }
        g_Y[f * (BS * Bc) + r] = make_float2(Y1, Y2);
    }
}

// ===================== K2: combine chunks sequentially per (b, j) =====================

__global__ void __launch_bounds__(256)
k2_combine(const float* __restrict__ q_init, const float* __restrict__ qd_init,
           const float* __restrict__ tke, const float* __restrict__ tkd,
           const float* __restrict__ bmass)
{
    const int t = blockIdx.x * 256 + threadIdx.x;   // 0..25599
    if (t >= BS * Bc) return;
    const int b = t / Bc;
    const int j = t - b * Bc;

    const float ke = tke[t];
    const float kd = tkd[t];
    const float invm = 1.f / (bmass[b*NBc + 1 + j] + 0.1f);
    const float al = DTc * invm * ke;
    const float Bb = 1.f - DTc * invm * kd;

    // per-step matrix M, then P = M^10
    const float M00 = 1.f - DTc * al, M01 = DTc * Bb;
    const float M10 = -al,            M11 = Bb;
    float P00 = M00, P01 = M01, P10 = M10, P11 = M11;
    #pragma unroll
    for (int i = 0; i < 9; i++) {
        float n00 = M00*P00 + M01*P10;
        float n01 = M00*P01 + M01*P11;
        float n10 = M10*P00 + M11*P10;
        float n11 = M10*P01 + M11*P11;
        P00 = n00; P01 = n01; P10 = n10; P11 = n11;
    }

    float X1 = q_init[b*ND + 7 + j];
    float X2 = qd_init[b*NDD + 6 + j];
    g_jsnap[t] = make_float2(X1, X2);
    #pragma unroll
    for (int f = 0; f < Fc; f++) {
        float2 Y = g_Y[f * (BS * Bc) + t];
        float n1 = P00*X1 + P01*X2 + Y.x;
        float n2 = P10*X1 + P11*X2 + Y.y;
        X1 = n1; X2 = n2;
        g_jsnap[(f + 1) * (BS * Bc) + t] = make_float2(X1, X2);
    }
}

// ===================== K3: forward kinematics per (frame, batch) warp =====================

__global__ void __launch_bounds__(256)
k3_fk(const float* __restrict__ jaxes, const float* __restrict__ joffs,
      float* __restrict__ out)
{
    const int w = blockIdx.x * 8 + (threadIdx.x >> 5);   // 0..16383
    const int lane = threadIdx.x & 31;
    const int f = w / BS;
    const int b = w - f * BS;

    const float* rs = g_root + ((size_t)f * BS + b) * 16;
    float px = rs[0], py = rs[1], pz = rs[2];
    float qx = rs[3], qy = rs[4], qz = rs[5], qw = rs[6];
    float wx = rs[7], wy = rs[8], wz = rs[9];
    float vx = rs[10], vy = rs[11], vz = rs[12];

    float jq = 0.f, jqd = 0.f;
    float ax = 0.f, ay = 0.f, az = 0.f, ox = 0.f, oy = 0.f, oz = 0.f;
    if (lane < Bc) {
        float2 s = g_jsnap[f * (BS * Bc) + b * Bc + lane];
        jq = s.x; jqd = s.y;
        float a0 = jaxes[lane*3 + 0], a1 = jaxes[lane*3 + 1], a2 = jaxes[lane*3 + 2];
        float n = fmaxf(sqrtf(a0*a0 + a1*a1 + a2*a2), 1e-8f);
        ax = a0 / n; ay = a1 / n; az = a2 / n;
        ox = joffs[lane*3 + 0]; oy = joffs[lane*3 + 1]; oz = joffs[lane*3 + 2];
    }

    // local joint rotation dq
    float sh, ch;
    sincosf(0.5f * jq, &sh, &ch);
    float Px = ax*sh, Py = ay*sh, Pz = az*sh, Pw = ch;

    // inclusive quaternion product scan
    #pragma unroll
    for (int o = 1; o < 32; o <<= 1) {
        float bx = __shfl_up_sync(0xffffffffu, Px, o);
        float by = __shfl_up_sync(0xffffffffu, Py, o);
        float bz = __shfl_up_sync(0xffffffffu, Pz, o);
        float bw = __shfl_up_sync(0xffffffffu, Pw, o);
        if (lane >= o) {
            float rx, ry, rz, rw;
            quat_mul(bx, by, bz, bw, Px, Py, Pz, Pw, rx, ry, rz, rw);
            Px = rx; Py = ry; Pz = rz; Pw = rw;
        }
    }
    float Ex = __shfl_up_sync(0xffffffffu, Px, 1);
    float Ey = __shfl_up_sync(0xffffffffu, Py, 1);
    float Ez = __shfl_up_sync(0xffffffffu, Pz, 1);
    float Ew = __shfl_up_sync(0xffffffffu, Pw, 1);
    if (lane == 0) { Ex = 0.f; Ey = 0.f; Ez = 0.f; Ew = 1.f; }

    float Qpx, Qpy, Qpz, Qpw, Qcx, Qcy, Qcz, Qcw;
    quat_mul(qx, qy, qz, qw, Ex, Ey, Ez, Ew, Qpx, Qpy, Qpz, Qpw);
    quat_mul(qx, qy, qz, qw, Px, Py, Pz, Pw, Qcx, Qcy, Qcz, Qcw);

    float owx, owy, owz, awx, awy, awz;
    quat_rot(Qpx, Qpy, Qpz, Qpw, ox, oy, oz, owx, owy, owz);
    quat_rot(Qpx, Qpy, Qpz, Qpw, ax, ay, az, awx, awy, awz);
    float dwx = awx * jqd, dwy = awy * jqd, dwz = awz * jqd;

    float Wx = dwx, Wy = dwy, Wz = dwz;
    SCAN3(Wx, Wy, Wz, lane);
    float wpx = wx + (Wx - dwx);
    float wpy = wy + (Wy - dwy);
    float wpz = wz + (Wz - dwz);

    float dvx = wpy*owz - wpz*owy;
    float dvy = wpz*owx - wpx*owz;
    float dvz = wpx*owy - wpy*owx;

    float Sx = owx, Sy = owy, Sz = owz;
    SCAN3(Sx, Sy, Sz, lane);
    float Vx = dvx, Vy = dvy, Vz = dvz;
    SCAN3(Vx, Vy, Vz, lane);

    const size_t posStride = (size_t)BS * NBc * 7;
    const size_t velStride = (size_t)BS * NBc * 6;
    const size_t POS_TOTAL = (size_t)(Fc + 1) * posStride;
    const size_t posBase = (size_t)f * posStride + (size_t)b * NBc * 7;
    const size_t velBase = POS_TOTAL + (size_t)f * velStride + (size_t)b * NBc * 6;

    if (lane == 0) {
        out[posBase + 0] = px; out[posBase + 1] = py; out[posBase + 2] = pz;
        out[posBase + 3] = qx; out[posBase + 4] = qy; out[posBase + 5] = qz; out[posBase + 6] = qw;
        out[velBase + 0] = wx; out[velBase + 1] = wy; out[velBase + 2] = wz;
        out[velBase + 3] = vx; out[velBase + 4] = vy; out[velBase + 5] = vz;
    }
    if (lane < Bc) {
        size_t pb = posBase + (size_t)(1 + lane) * 7;
        out[pb + 0] = px + Sx; out[pb + 1] = py + Sy; out[pb + 2] = pz + Sz;
        out[pb + 3] = Qcx; out[pb + 4] = Qcy; out[pb + 5] = Qcz; out[pb + 6] = Qcw;
        size_t vb = velBase + (size_t)(1 + lane) * 6;
        out[vb + 0] = wx + Wx; out[vb + 1] = wy + Wy; out[vb + 2] = wz + Wz;
        out[vb + 3] = vx + Vx; out[vb + 4] = vy + Vy; out[vb + 5] = vz + Vz;
    }
}

extern "C" void kernel_launch(void* const* d_in, const int* in_sizes, int n_in,
                              void* d_out, int out_size)
{
    const float* q_init   = (const float*)d_in[0];
    const float* qd_init  = (const float*)d_in[1];
    const float* torques  = (const float*)d_in[2];
    const float* res_f    = (const float*)d_in[3];
    const float* refs     = (const float*)d_in[4];
    const float* tke      = (const float*)d_in[5];
    const float* tkd      = (const float*)d_in[6];
    const float* bmass    = (const float*)d_in[7];
    const float* jaxes    = (const float*)d_in[8];
    const float* joffs    = (const float*)d_in[9];
    float* out = (float*)d_out;

    k1_integrate<<<ROOT_BLOCKS + J_BLOCKS, 256>>>(
        q_init, qd_init, torques, res_f, refs, tke, tkd, bmass, jaxes);
    k2_combine<<<(BS * Bc + 255) / 256, 256>>>(q_init, qd_init, tke, tkd, bmass);
    k3_fk<<<((Fc + 1) * BS) / 8, 256>>>(jaxes, joffs, out);
}

// round 5
// speedup vs baseline: 1.1879x; 1.1879x over previous
#include <cuda_runtime.h>
#include <cstdint>

#define DTc 0.0005f
#define BS 1024
#define Bc 25
#define NBc 26
#define Fc 15
#define SPFc 10
#define NCH 30     // chunks (5 steps each)
#define CSTEP 5
#define ND 32      // 7 + B
#define NDD 31     // 6 + B
#define RFROW 156  // (B+1)*6

#define ROOT_BLOCKS 128
#define ROOT_WPB 8
#define JBLK_PER_C 100            // 25600 / 256
#define J_BLOCKS (NCH * JBLK_PER_C)

// ---- device scratch (static; no allocation) ----
__device__ float2 g_Y[NCH * BS * Bc];          // per-chunk affine offsets
__device__ float  g_root[(Fc + 1) * BS * 16];  // root p,q,w,v (13 used) per frame

__device__ __forceinline__ void cp4(float* dst, const float* src) {
    unsigned d = (unsigned)__cvta_generic_to_shared(dst);
    asm volatile("cp.async.ca.shared.global [%0], [%1], 4;\n" :: "r"(d), "l"(src));
}
__device__ __forceinline__ void cp_commit() { asm volatile("cp.async.commit_group;\n"); }
__device__ __forceinline__ void cp_wait0()  { asm volatile("cp.async.wait_group 0;\n"); }

__device__ __forceinline__ void quat_mul(
    float ax, float ay, float az, float aw,
    float bx, float by, float bz, float bw,
    float& rx, float& ry, float& rz, float& rw)
{
    rx = aw*bx + ax*bw + ay*bz - az*by;
    ry = aw*by - ax*bz + ay*bw + az*bx;
    rz = aw*bz + ax*by - ay*bx + az*bw;
    rw = aw*bw - ax*bx - ay*by - az*bz;
}

__device__ __forceinline__ void quat_rot(
    float qx, float qy, float qz, float qw,
    float vx, float vy, float vz,
    float& rx, float& ry, float& rz)
{
    float tx = 2.f*(qy*vz - qz*vy);
    float ty = 2.f*(qz*vx - qx*vz);
    float tz = 2.f*(qx*vy - qy*vx);
    rx = vx + qw*tx + (qy*tz - qz*ty);
    ry = vy + qw*ty + (qz*tx - qx*tz);
    rz = vz + qw*tz + (qx*ty - qy*tx);
}

#define SCAN3(X, Y, Z, lane)                                              \
    _Pragma("unroll")                                                     \
    for (int _o = 1; _o < 32; _o <<= 1) {                                 \
        float _tx = __shfl_up_sync(0xffffffffu, X, _o);                   \
        float _ty = __shfl_up_sync(0xffffffffu, Y, _o);                   \
        float _tz = __shfl_up_sync(0xffffffffu, Z, _o);                   \
        if ((lane) >= _o) { X += _tx; Y += _ty; Z += _tz; }               \
    }

// ===================== K1: time-chunk joint integration + root chain =====================

__device__ __forceinline__ void stage_root(
    float* __restrict__ buf, int lane, int f, int b,
    const float* __restrict__ torques, const float* __restrict__ res_f)
{
    const int s0 = f * SPFc;
    #pragma unroll
    for (int s = 0; s < SPFc; s++) {
        const float* rT = torques + ((size_t)(s0 + s) * BS + b) * NDD;
        const float* rF = res_f   + ((size_t)(s0 + s) * BS + b) * RFROW;
        if (lane < 6)       cp4(buf + s*12 + lane, rT + lane);
        else if (lane < 12) cp4(buf + s*12 + lane, rF + (lane - 6));
    }
}

__global__ void __launch_bounds__(256)
k1_integrate(const float* __restrict__ q_init, const float* __restrict__ qd_init,
             const float* __restrict__ torques, const float* __restrict__ res_f,
             const float* __restrict__ refs, const float* __restrict__ tke,
             const float* __restrict__ tkd, const float* __restrict__ bmass,
             const float* __restrict__ jaxes)
{
    __shared__ float sroot[ROOT_WPB][2][SPFc * 12];

    if (blockIdx.x < ROOT_BLOCKS) {
        // ---------------- root integration: one warp per batch element ----------------
        const int warp = threadIdx.x >> 5;
        const int lane = threadIdx.x & 31;
        const int b = blockIdx.x * ROOT_WPB + warp;

        float px = q_init[b*ND + 0], py = q_init[b*ND + 1], pz = q_init[b*ND + 2];
        float qx = q_init[b*ND + 3], qy = q_init[b*ND + 4], qz = q_init[b*ND + 5], qw = q_init[b*ND + 6];
        {
            float n2 = qx*qx + qy*qy + qz*qz + qw*qw;
            float inv = rsqrtf(fmaxf(n2, 1e-16f));
            qx *= inv; qy *= inv; qz *= inv; qw *= inv;
        }
        float wx = qd_init[b*NDD + 0], wy = qd_init[b*NDD + 1], wz = qd_init[b*NDD + 2];
        float vx = qd_init[b*NDD + 3], vy = qd_init[b*NDD + 4], vz = qd_init[b*NDD + 5];
        const float invm0 = 1.f / (bmass[b*NBc + 0] + 0.1f);

        if (lane == 0) {
            float* d = g_root + (size_t)b * 16;
            d[0]=px; d[1]=py; d[2]=pz; d[3]=qx; d[4]=qy; d[5]=qz; d[6]=qw;
            d[7]=wx; d[8]=wy; d[9]=wz; d[10]=vx; d[11]=vy; d[12]=vz;
        }

        float* buf0 = sroot[warp][0];
        float* buf1 = sroot[warp][1];
        stage_root(buf0, lane, 0, b, torques, res_f);
        cp_commit(); cp_wait0(); __syncwarp();

        for (int f = 0; f < Fc; f++) {
            float* cur = (f & 1) ? buf1 : buf0;
            float* nxt = (f & 1) ? buf0 : buf1;
            if (f + 1 < Fc) { stage_root(nxt, lane, f + 1, b, torques, res_f); cp_commit(); }

            #pragma unroll
            for (int s = 0; s < SPFc; s++) {
                const float* u = cur + s * 12;
                vx += DTc * ((u[3] + u[9])  * invm0);
                vy += DTc * ((u[4] + u[10]) * invm0);
                vz += DTc * ((u[5] + u[11]) * invm0 - 9.81f);
                wx += DTc * ((u[0] + u[6]) * invm0);
                wy += DTc * ((u[1] + u[7]) * invm0);
                wz += DTc * ((u[2] + u[8]) * invm0);
                px += DTc * vx; py += DTc * vy; pz += DTc * vz;
                float mx =  wx*qw + wy*qz - wz*qy;
                float my = -wx*qz + wy*qw + wz*qx;
                float mz =  wx*qy - wy*qx + wz*qw;
                float mw = -(wx*qx + wy*qy + wz*qz);
                qx += 0.5f * DTc * mx; qy += 0.5f * DTc * my;
                qz += 0.5f * DTc * mz; qw += 0.5f * DTc * mw;
                float n2 = qx*qx + qy*qy + qz*qz + qw*qw;
                float inv = rsqrtf(fmaxf(n2, 1e-16f));
                qx *= inv; qy *= inv; qz *= inv; qw *= inv;
            }

            if (lane == 0) {
                float* d = g_root + ((size_t)(f + 1) * BS + b) * 16;
                d[0]=px; d[1]=py; d[2]=pz; d[3]=qx; d[4]=qy; d[5]=qz; d[6]=qw;
                d[7]=wx; d[8]=wy; d[9]=wz; d[10]=vx; d[11]=vy; d[12]=vz;
            }
            if (f + 1 < Fc) { cp_wait0(); __syncwarp(); }
        }
    } else {
        // ------------- joint chunks: thread = (chunk c, batch b, joint j), 5 steps -------------
        const int jb = blockIdx.x - ROOT_BLOCKS;
        const int c = jb / JBLK_PER_C;
        const int r = (jb % JBLK_PER_C) * 256 + threadIdx.x;  // 0..25599
        const int b = r / Bc;
        const int j = r - b * Bc;

        const float ke = tke[r];
        const float kd = tkd[r];
        const float invm = 1.f / (bmass[b*NBc + 1 + j] + 0.1f);
        const float al = DTc * invm * ke;       // alpha
        const float Bb = 1.f - DTc * invm * kd; // 1 - kappa
        float a0 = jaxes[j*3 + 0], a1 = jaxes[j*3 + 1], a2 = jaxes[j*3 + 2];
        {
            float n = fmaxf(sqrtf(a0*a0 + a1*a1 + a2*a2), 1e-8f);
            a0 /= n; a1 /= n; a2 /= n;
        }

        const int s0 = c * CSTEP;
        float tv[CSTEP], rv[CSTEP], fz[CSTEP];
        float2 fxy[CSTEP];
        #pragma unroll
        for (int k = 0; k < CSTEP; k++) {
            const int s = s0 + k;
            const size_t rowT = ((size_t)s * BS + b) * NDD;
            tv[k] = __ldcs(torques + rowT + 6 + j);
            rv[k] = __ldcs(refs + rowT + 6 + j);
            const size_t rowF = (((size_t)s * BS + b) * NBc + 1 + j) * 6;
            fxy[k] = __ldcs((const float2*)(res_f + rowF));
            fz[k]  = __ldcs(res_f + rowF + 2);
        }
        float Y1 = 0.f, Y2 = 0.f;
        #pragma unroll
        for (int k = 0; k < CSTEP; k++) {
            float cc = DTc * invm * (tv[k] + ke * rv[k] + fxy[k].x*a0 + fxy[k].y*a1 + fz[k]*a2);
            float y2 = fmaf(-al, Y1, fmaf(Bb, Y2, cc));
            Y1 = fmaf(DTc, y2, Y1);
            Y2 = y2;
        }
        g_Y[c * (BS * Bc) + r] = make_float2(Y1, Y2);
    }
}

// ===================== K23: combine + FK, one block per batch =====================

__global__ void __launch_bounds__(256)
k23_combine_fk(const float* __restrict__ q_init, const float* __restrict__ qd_init,
               const float* __restrict__ tke, const float* __restrict__ tkd,
               const float* __restrict__ bmass,
               const float* __restrict__ jaxes, const float* __restrict__ joffs,
               float* __restrict__ out)
{
    __shared__ float  sroot[Fc + 1][16];
    __shared__ float2 sj[Fc + 1][Bc];

    const int b = blockIdx.x;
    const int t = threadIdx.x;
    const int warp = t >> 5;
    const int lane = t & 31;

    // load 16 root states (13 floats each)
    if (t < (Fc + 1) * 13) {
        int f = t / 13, k = t - f * 13;
        sroot[f][k] = g_root[((size_t)f * BS + b) * 16 + k];
    }

    // combine chunks: 25 threads, 30 sequential chunks (snapshot every 2nd)
    if (t < Bc) {
        const int j = t;
        const float ke = tke[b*Bc + j];
        const float kd = tkd[b*Bc + j];
        const float invm = 1.f / (bmass[b*NBc + 1 + j] + 0.1f);
        const float al = DTc * invm * ke;
        const float Bb = 1.f - DTc * invm * kd;

        // per-step matrix M, then P = M^5
        const float M00 = 1.f - DTc * al, M01 = DTc * Bb;
        const float M10 = -al,            M11 = Bb;
        float P00 = M00, P01 = M01, P10 = M10, P11 = M11;
        #pragma unroll
        for (int i = 0; i < 4; i++) {
            float n00 = M00*P00 + M01*P10;
            float n01 = M00*P01 + M01*P11;
            float n10 = M10*P00 + M11*P10;
            float n11 = M10*P01 + M11*P11;
            P00 = n00; P01 = n01; P10 = n10; P11 = n11;
        }

        float X1 = q_init[b*ND + 7 + j];
        float X2 = qd_init[b*NDD + 6 + j];
        sj[0][j] = make_float2(X1, X2);
        #pragma unroll
        for (int c = 0; c < NCH; c++) {
            float2 Y = g_Y[c * (BS * Bc) + b * Bc + j];
            float n1 = P00*X1 + P01*X2 + Y.x;
            float n2 = P10*X1 + P11*X2 + Y.y;
            X1 = n1; X2 = n2;
            if (c & 1) sj[(c + 1) >> 1][j] = make_float2(X1, X2);
        }
    }
    __syncthreads();

    // per-lane constants
    float ax = 0.f, ay = 0.f, az = 0.f, ox = 0.f, oy = 0.f, oz = 0.f;
    if (lane < Bc) {
        float a0 = jaxes[lane*3 + 0], a1 = jaxes[lane*3 + 1], a2 = jaxes[lane*3 + 2];
        float n = fmaxf(sqrtf(a0*a0 + a1*a1 + a2*a2), 1e-8f);
        ax = a0 / n; ay = a1 / n; az = a2 / n;
        ox = joffs[lane*3 + 0]; oy = joffs[lane*3 + 1]; oz = joffs[lane*3 + 2];
    }

    const size_t posStride = (size_t)BS * NBc * 7;
    const size_t velStride = (size_t)BS * NBc * 6;
    const size_t POS_TOTAL = (size_t)(Fc + 1) * posStride;

    #pragma unroll
    for (int it = 0; it < 2; it++) {
        const int f = warp + it * 8;   // 0..15

        const float* rs = sroot[f];
        float px = rs[0], py = rs[1], pz = rs[2];
        float qx = rs[3], qy = rs[4], qz = rs[5], qw = rs[6];
        float wx = rs[7], wy = rs[8], wz = rs[9];
        float vx = rs[10], vy = rs[11], vz = rs[12];

        float jq = 0.f, jqd = 0.f;
        if (lane < Bc) { float2 s = sj[f][lane]; jq = s.x; jqd = s.y; }

        float sh, ch;
        sincosf(0.5f * jq, &sh, &ch);
        float Px = ax*sh, Py = ay*sh, Pz = az*sh, Pw = ch;

        #pragma unroll
        for (int o = 1; o < 32; o <<= 1) {
            float bx = __shfl_up_sync(0xffffffffu, Px, o);
            float by = __shfl_up_sync(0xffffffffu, Py, o);
            float bz = __shfl_up_sync(0xffffffffu, Pz, o);
            float bw = __shfl_up_sync(0xffffffffu, Pw, o);
            if (lane >= o) {
                float rx, ry, rz, rw;
                quat_mul(bx, by, bz, bw, Px, Py, Pz, Pw, rx, ry, rz, rw);
                Px = rx; Py = ry; Pz = rz; Pw = rw;
            }
        }
        float Ex = __shfl_up_sync(0xffffffffu, Px, 1);
        float Ey = __shfl_up_sync(0xffffffffu, Py, 1);
        float Ez = __shfl_up_sync(0xffffffffu, Pz, 1);
        float Ew = __shfl_up_sync(0xffffffffu, Pw, 1);
        if (lane == 0) { Ex = 0.f; Ey = 0.f; Ez = 0.f; Ew = 1.f; }

        float Qpx, Qpy, Qpz, Qpw, Qcx, Qcy, Qcz, Qcw;
        quat_mul(qx, qy, qz, qw, Ex, Ey, Ez, Ew, Qpx, Qpy, Qpz, Qpw);
        quat_mul(qx, qy, qz, qw, Px, Py, Pz, Pw, Qcx, Qcy, Qcz, Qcw);

        float owx, owy, owz, awx, awy, awz;
        quat_rot(Qpx, Qpy, Qpz, Qpw, ox, oy, oz, owx, owy, owz);
        quat_rot(Qpx, Qpy, Qpz, Qpw, ax, ay, az, awx, awy, awz);
        float dwx = awx * jqd, dwy = awy * jqd, dwz = awz * jqd;

        float Wx = dwx, Wy = dwy, Wz = dwz;
        SCAN3(Wx, Wy, Wz, lane);
        float wpx = wx + (Wx - dwx);
        float wpy = wy + (Wy - dwy);
        float wpz = wz + (Wz - dwz);

        float dvx = wpy*owz - wpz*owy;
        float dvy = wpz*owx - wpx*owz;
        float dvz = wpx*owy - wpy*owx;

        float Sx = owx, Sy = owy, Sz = owz;
        SCAN3(Sx, Sy, Sz, lane);
        float Vx = dvx, Vy = dvy, Vz = dvz;
        SCAN3(Vx, Vy, Vz, lane);

        const size_t posBase = (size_t)f * posStride + (size_t)b * NBc * 7;
        const size_t velBase = POS_TOTAL + (size_t)f * velStride + (size_t)b * NBc * 6;

        if (lane == 0) {
            out[posBase + 0] = px; out[posBase + 1] = py; out[posBase + 2] = pz;
            out[posBase + 3] = qx; out[posBase + 4] = qy; out[posBase + 5] = qz; out[posBase + 6] = qw;
            out[velBase + 0] = wx; out[velBase + 1] = wy; out[velBase + 2] = wz;
            out[velBase + 3] = vx; out[velBase + 4] = vy; out[velBase + 5] = vz;
        }
        if (lane < Bc) {
            size_t pb = posBase + (size_t)(1 + lane) * 7;
            out[pb + 0] = px + Sx; out[pb + 1] = py + Sy; out[pb + 2] = pz + Sz;
            out[pb + 3] = Qcx; out[pb + 4] = Qcy; out[pb + 5] = Qcz; out[pb + 6] = Qcw;
            size_t vb = velBase + (size_t)(1 + lane) * 6;
            out[vb + 0] = wx + Wx; out[vb + 1] = wy + Wy; out[vb + 2] = wz + Wz;
            out[vb + 3] = vx + Vx; out[vb + 4] = vy + Vy; out[vb + 5] = vz + Vz;
        }
    }
}

extern "C" void kernel_launch(void* const* d_in, const int* in_sizes, int n_in,
                              void* d_out, int out_size)
{
    const float* q_init   = (const float*)d_in[0];
    const float* qd_init  = (const float*)d_in[1];
    const float* torques  = (const float*)d_in[2];
    const float* res_f    = (const float*)d_in[3];
    const float* refs     = (const float*)d_in[4];
    const float* tke      = (const float*)d_in[5];
    const float* tkd      = (const float*)d_in[6];
    const float* bmass    = (const float*)d_in[7];
    const float* jaxes    = (const float*)d_in[8];
    const float* joffs    = (const float*)d_in[9];
    float* out = (float*)d_out;

    k1_integrate<<<ROOT_BLOCKS + J_BLOCKS, 256>>>(
        q_init, qd_init, torques, res_f, refs, tke, tkd, bmass, jaxes);
    k23_combine_fk<<<BS, 256>>>(q_init, qd_init, tke, tkd, bmass, jaxes, joffs, out);
}